// round 7
// baseline (speedup 1.0000x reference)
#include <cuda_runtime.h>

// FeedForwardQuantum — two-phase unidirectional streaming.
//   Phase A (read-only stream):  q[t] = cos(dot(x[t,:],W1)+b1)*cos(phi)
//                                -> 128 KB scratch (L2-resident)
//   Phase B (write-only stream): out[t,d] = q[t]*W2[d] + b2[d]
// Rationale: single fused kernel plateaued at 6.7 TB/s (mixed read+write).
// Unidirectional HBM streams avoid bus-turnaround loss; the A->B
// intermediate is only 32768 floats.

#define EMBED_F4       256   // float4s per token row
#define WARPS_PER_CTA    8
#define THREADS        (WARPS_PER_CTA * 32)
#define MAX_TOKENS   32768

__device__ float g_q[MAX_TOKENS];

// ---------------- Phase A: read x, compute q ----------------
__global__ __launch_bounds__(THREADS, 8)
void ffq_phaseA(const float4* __restrict__ x,
                const float4* __restrict__ W1,
                const float*  __restrict__ b1,
                const float*  __restrict__ phi)
{
    const int warp = threadIdx.x >> 5;
    const int lane = threadIdx.x & 31;
    const long token = (long)blockIdx.x * WARPS_PER_CTA + warp;
    const long rbase = token * EMBED_F4 + lane;

    float p = 0.0f;
    // Two batches of 4 front-batched streaming loads (keeps regs <= 32).
    {
        float4 xv[4];
        #pragma unroll
        for (int i = 0; i < 4; i++)
            xv[i] = __ldcs(&x[rbase + 32 * i]);
        #pragma unroll
        for (int i = 0; i < 4; i++) {
            const float4 wv = W1[lane + 32 * i];   // L1-resident
            p = fmaf(xv[i].x, wv.x,
                fmaf(xv[i].y, wv.y,
                fmaf(xv[i].z, wv.z,
                fmaf(xv[i].w, wv.w, p))));
        }
    }
    {
        float4 xv[4];
        #pragma unroll
        for (int i = 0; i < 4; i++)
            xv[i] = __ldcs(&x[rbase + 32 * (i + 4)]);
        #pragma unroll
        for (int i = 0; i < 4; i++) {
            const float4 wv = W1[lane + 32 * (i + 4)];
            p = fmaf(xv[i].x, wv.x,
                fmaf(xv[i].y, wv.y,
                fmaf(xv[i].z, wv.z,
                fmaf(xv[i].w, wv.w, p))));
        }
    }

    #pragma unroll
    for (int o = 16; o > 0; o >>= 1)
        p += __shfl_xor_sync(0xffffffffu, p, o);

    if (lane == 0)
        g_q[token] = __cosf(p + b1[0]) * __cosf(phi[0]);
}

// ---------------- Phase B: broadcast q, stream out ----------------
__global__ __launch_bounds__(THREADS, 8)
void ffq_phaseB(const float4* __restrict__ W2,
                const float4* __restrict__ b2,
                float4* __restrict__ out)
{
    const int warp = threadIdx.x >> 5;
    const int lane = threadIdx.x & 31;
    const long token = (long)blockIdx.x * WARPS_PER_CTA + warp;
    const long rbase = token * EMBED_F4 + lane;

    const float q = g_q[token];   // L2-resident 128 KB, warp-broadcast

    #pragma unroll
    for (int i = 0; i < 8; i++) {
        const float4 w2 = W2[lane + 32 * i];   // L1-resident
        const float4 bb = b2[lane + 32 * i];
        float4 o;
        o.x = fmaf(q, w2.x, bb.x);
        o.y = fmaf(q, w2.y, bb.y);
        o.z = fmaf(q, w2.z, bb.z);
        o.w = fmaf(q, w2.w, bb.w);
        __stcs(&out[rbase + 32 * i], o);
    }
}

extern "C" void kernel_launch(void* const* d_in, const int* in_sizes, int n_in,
                              void* d_out, int out_size)
{
    const float4* x   = (const float4*)d_in[0];
    const float4* W1  = (const float4*)d_in[1];
    const float*  b1  = (const float*) d_in[2];
    const float*  phi = (const float*) d_in[3];
    const float4* W2  = (const float4*)d_in[4];
    const float4* b2  = (const float4*)d_in[5];
    float4* out = (float4*)d_out;

    const int tokens = in_sizes[0] / (EMBED_F4 * 4);   // 32768
    const int ctas   = tokens / WARPS_PER_CTA;         // 4096

    ffq_phaseA<<<ctas, THREADS>>>(x, W1, b1, phi);
    ffq_phaseB<<<ctas, THREADS>>>(W2, b2, out);        // same stream: ordered
}

// round 9
// speedup vs baseline: 1.0831x; 1.0831x over previous
#include <cuda_runtime.h>

// FeedForwardQuantum — fused warp-per-token + smem-staged weights.
//   theta = dot(x_row, W1) + b1 ; out = cos(theta)*cos(phi) * W2 + b2
// EMBED_DIM=1024 (256 float4), tokens = 32768.
//
// R5 structure (fused mixed stream = 6.7 TB/s, beats unidirectional
// two-phase which measured 5.5-6.0 TB/s per phase), with one change:
// W1/W2/b2 staged in 12KB smem per CTA. That moves 24 of 40 memory
// instructions per token off the L1tex wavefront queue (global path)
// onto the shared pipe, leaving L1tex purely for the DRAM-critical
// x loads + out stores. Occupancy preserved: <=32 regs, 8 CTAs/SM
// (96KB smem/SM < 228KB).

#define EMBED_F4       256   // float4s per token row
#define WARPS_PER_CTA    8
#define THREADS        (WARPS_PER_CTA * 32)

__global__ __launch_bounds__(THREADS, 8)
void ffq_kernel(const float4* __restrict__ x,
                const float4* __restrict__ W1,
                const float*  __restrict__ b1,
                const float*  __restrict__ phi,
                const float4* __restrict__ W2,
                const float4* __restrict__ b2,
                float4* __restrict__ out)
{
    __shared__ float4 sW1[EMBED_F4];
    __shared__ float4 sW2[EMBED_F4];
    __shared__ float4 sB2[EMBED_F4];

    const int tid = threadIdx.x;
    sW1[tid] = W1[tid];          // 256 threads x 1 float4 each
    sW2[tid] = W2[tid];
    sB2[tid] = b2[tid];
    __syncthreads();

    const int warp = tid >> 5;
    const int lane = tid & 31;
    const long token = (long)blockIdx.x * WARPS_PER_CTA + warp;
    const long rbase = token * EMBED_F4 + lane;

    float p = 0.0f;

    // Batch 1: 4 front-batched streaming loads, then consume vs smem W1.
    {
        float4 xv[4];
        #pragma unroll
        for (int i = 0; i < 4; i++)
            xv[i] = __ldcs(&x[rbase + 32 * i]);
        #pragma unroll
        for (int i = 0; i < 4; i++) {
            const float4 wv = sW1[lane + 32 * i];
            p = fmaf(xv[i].x, wv.x,
                fmaf(xv[i].y, wv.y,
                fmaf(xv[i].z, wv.z,
                fmaf(xv[i].w, wv.w, p))));
        }
    }
    // Batch 2.
    {
        float4 xv[4];
        #pragma unroll
        for (int i = 0; i < 4; i++)
            xv[i] = __ldcs(&x[rbase + 32 * (i + 4)]);
        #pragma unroll
        for (int i = 0; i < 4; i++) {
            const float4 wv = sW1[lane + 32 * (i + 4)];
            p = fmaf(xv[i].x, wv.x,
                fmaf(xv[i].y, wv.y,
                fmaf(xv[i].z, wv.z,
                fmaf(xv[i].w, wv.w, p))));
        }
    }

    // Warp-only reduction.
    #pragma unroll
    for (int o = 16; o > 0; o >>= 1)
        p += __shfl_xor_sync(0xffffffffu, p, o);

    const float q = __cosf(p + b1[0]) * __cosf(phi[0]);

    // out = q * W2 + b2 from smem; streaming stores.
    #pragma unroll
    for (int i = 0; i < 8; i++) {
        const float4 w2 = sW2[lane + 32 * i];
        const float4 bb = sB2[lane + 32 * i];
        float4 o;
        o.x = fmaf(q, w2.x, bb.x);
        o.y = fmaf(q, w2.y, bb.y);
        o.z = fmaf(q, w2.z, bb.z);
        o.w = fmaf(q, w2.w, bb.w);
        __stcs(&out[rbase + 32 * i], o);
    }
}

extern "C" void kernel_launch(void* const* d_in, const int* in_sizes, int n_in,
                              void* d_out, int out_size)
{
    const float4* x   = (const float4*)d_in[0];
    const float4* W1  = (const float4*)d_in[1];
    const float*  b1  = (const float*) d_in[2];
    const float*  phi = (const float*) d_in[3];
    const float4* W2  = (const float4*)d_in[4];
    const float4* b2  = (const float4*)d_in[5];
    float4* out = (float4*)d_out;

    const int tokens = in_sizes[0] / (EMBED_F4 * 4);   // 32768
    ffq_kernel<<<tokens / WARPS_PER_CTA, THREADS>>>(x, W1, b1, phi, W2, b2, out);
}